// round 14
// baseline (speedup 1.0000x reference)
#include <cuda_runtime.h>
#include <mma.h>
#include <cstdint>
#include <cstdio>

using namespace nvcuda;

// Problem constants
#define BB   16
#define NSEQ 512
#define DM   768
#define HH   12
#define DK   64
#define NDE  32

#define MTOT (BB * NSEQ)   // 8192 rows

// ---------------- scratch (device globals; allocation-free) ----------------
__device__ float g_xln[MTOT * DM];
__device__ float g_q[MTOT * DM];     // head-major (B,H,N,DK)
__device__ float g_k[MTOT * DM];     // head-major
__device__ float g_v[MTOT * DM];     // head-major
__device__ float g_oh[MTOT * DM];    // token-major (B,N,D)
__device__ int   g_px[MTOT];
__device__ int   g_py[MTOT];

// ---------------- LayerNorm ----------------
__global__ __launch_bounds__(256) void ln_kernel(const float* __restrict__ x,
                                                 const float* __restrict__ gamma,
                                                 const float* __restrict__ beta,
                                                 float* __restrict__ y) {
    int row = blockIdx.x;
    int tid = threadIdx.x;
    const float* xr = x + (size_t)row * DM;
    float v0 = xr[tid], v1 = xr[tid + 256], v2 = xr[tid + 512];
    __shared__ float red[256];
    red[tid] = v0 + v1 + v2;
    __syncthreads();
    for (int o = 128; o; o >>= 1) { if (tid < o) red[tid] += red[tid + o]; __syncthreads(); }
    float mean = red[0] * (1.0f / 768.0f);
    __syncthreads();
    float d0 = v0 - mean, d1 = v1 - mean, d2 = v2 - mean;
    red[tid] = d0 * d0 + d1 * d1 + d2 * d2;
    __syncthreads();
    for (int o = 128; o; o >>= 1) { if (tid < o) red[tid] += red[tid + o]; __syncthreads(); }
    float rs = rsqrtf(red[0] * (1.0f / 768.0f) + 1e-5f);
    float* yr = y + (size_t)row * DM;
    yr[tid]       = d0 * rs * gamma[tid]       + beta[tid];
    yr[tid + 256] = d1 * rs * gamma[tid + 256] + beta[tid + 256];
    yr[tid + 512] = d2 * rs * gamma[tid + 512] + beta[tid + 512];
}

// ---------------- Patch bins ----------------
__global__ void bins_kernel(const float* __restrict__ boxes,
                            const int* __restrict__ img,
                            int* __restrict__ px, int* __restrict__ py) {
    int t = blockIdx.x * blockDim.x + threadIdx.x;
    if (t >= MTOT) return;
    int b = t / NSEQ;
    float wf = (float)img[b * 4 + 0];
    float hf = (float)img[b * 4 + 1];
    const float* bx = boxes + (size_t)t * 4;
    float spa_w = floorf(wf / 11.0f);
    float spa_h = floorf(hf / 11.0f);
    float cx = floorf((bx[0] * wf + bx[2] * wf) * 0.5f);
    float cy = floorf((bx[1] * hf + bx[3] * hf) * 0.5f);
    int pxi = 0, pyi = 0;
    for (int i = 0; i < 11; i++) {
        float lo = (float)i * spa_w, hi = (float)(i + 1) * spa_w;
        if (lo <= cx && cx <= hi) { pxi = i; break; }
    }
    for (int i = 0; i < 11; i++) {
        float lo = (float)i * spa_h, hi = (float)(i + 1) * spa_h;
        if (lo <= cy && cy <= hi) { pyi = i; break; }
    }
    px[t] = pxi;
    py[t] = pyi;
}

// ---------------- 3-stage pipelined TF32 GEMM: C = A @ W^T + bias ----------------
#define GBM 128
#define GBN 128
#define GBK 32
#define GLD 36
#define GST 3

__device__ __forceinline__ void cp_async16(void* smem, const void* gmem) {
    uint32_t s = (uint32_t)__cvta_generic_to_shared(smem);
    asm volatile("cp.async.cg.shared.global [%0], [%1], 16;\n" :: "r"(s), "l"(gmem));
}

__global__ __launch_bounds__(256, 2) void gemm_tf32_pipe(
    const float* __restrict__ A,
    const float* __restrict__ W0, const float* __restrict__ W1, const float* __restrict__ W2,
    const float* __restrict__ b0, const float* __restrict__ b1, const float* __restrict__ b2,
    float* __restrict__ C0, float* __restrict__ C1, float* __restrict__ C2,
    int M, int Nn, int K, int headmajor)
{
    extern __shared__ float sm[];
    float* As = sm;                        // [3][GBM][GLD]
    float* Bs = sm + GST * GBM * GLD;      // [3][GBN][GLD]

    const float* W    = blockIdx.z == 0 ? W0 : blockIdx.z == 1 ? W1 : W2;
    const float* bias = blockIdx.z == 0 ? b0 : blockIdx.z == 1 ? b1 : b2;
    float*       C    = blockIdx.z == 0 ? C0 : blockIdx.z == 1 ? C1 : C2;

    int tid = threadIdx.x;
    int w = tid >> 5, lane = tid & 31;
    int wm = w >> 2, wn = w & 3;
    int m0 = blockIdx.y * GBM;
    int n0 = blockIdx.x * GBN;

    wmma::fragment<wmma::accumulator, 16, 16, 8, float> acc[4][2];
    #pragma unroll
    for (int i = 0; i < 4; i++)
        #pragma unroll
        for (int j = 0; j < 2; j++) wmma::fill_fragment(acc[i][j], 0.0f);

    int r_ld  = tid >> 3;
    int c4_ld = (tid & 7) * 4;

    const int NIT = K / GBK;

    // prologue: chunks 0,1 -> bufs 0,1 (one commit group each)
    #pragma unroll
    for (int pc = 0; pc < 2; pc++) {
        float* Ab = As + pc * GBM * GLD;
        float* Bb = Bs + pc * GBN * GLD;
        int k0 = pc * GBK;
        #pragma unroll
        for (int j = 0; j < 4; j++) {
            int r = r_ld + j * 32;
            cp_async16(Ab + r * GLD + c4_ld, A + (size_t)(m0 + r) * K + k0 + c4_ld);
            cp_async16(Bb + r * GLD + c4_ld, W + (size_t)(n0 + r) * K + k0 + c4_ld);
        }
        asm volatile("cp.async.commit_group;\n" ::: "memory");
    }

    for (int it = 0; it < NIT; it++) {
        asm volatile("cp.async.wait_group 1;\n" ::: "memory");
        __syncthreads();
        int in = it + 2;
        if (in < NIT) {
            int k0 = in * GBK;
            float* Ab = As + (in % GST) * GBM * GLD;
            float* Bb = Bs + (in % GST) * GBN * GLD;
            #pragma unroll
            for (int j = 0; j < 4; j++) {
                int r = r_ld + j * 32;
                cp_async16(Ab + r * GLD + c4_ld, A + (size_t)(m0 + r) * K + k0 + c4_ld);
                cp_async16(Bb + r * GLD + c4_ld, W + (size_t)(n0 + r) * K + k0 + c4_ld);
            }
        }
        asm volatile("cp.async.commit_group;\n" ::: "memory");   // always (empty at tail)

        float* Ab = As + (it % GST) * GBM * GLD;
        float* Bb = Bs + (it % GST) * GBN * GLD;
        #pragma unroll
        for (int ks = 0; ks < 4; ks++) {
            wmma::fragment<wmma::matrix_a, 16, 16, 8, wmma::precision::tf32, wmma::row_major> af[4];
            wmma::fragment<wmma::matrix_b, 16, 16, 8, wmma::precision::tf32, wmma::col_major> bf[2];
            #pragma unroll
            for (int mi = 0; mi < 4; mi++) {
                wmma::load_matrix_sync(af[mi], Ab + (wm * 64 + mi * 16) * GLD + ks * 8, GLD);
                #pragma unroll
                for (int e = 0; e < af[mi].num_elements; e++)
                    af[mi].x[e] = wmma::__float_to_tf32(af[mi].x[e]);
            }
            #pragma unroll
            for (int ni = 0; ni < 2; ni++) {
                wmma::load_matrix_sync(bf[ni], Bb + (wn * 32 + ni * 16) * GLD + ks * 8, GLD);
                #pragma unroll
                for (int e = 0; e < bf[ni].num_elements; e++)
                    bf[ni].x[e] = wmma::__float_to_tf32(bf[ni].x[e]);
            }
            #pragma unroll
            for (int mi = 0; mi < 4; mi++)
                #pragma unroll
                for (int ni = 0; ni < 2; ni++)
                    wmma::mma_sync(acc[mi][ni], af[mi], bf[ni], acc[mi][ni]);
        }
    }
    __syncthreads();

    float* stg = sm + w * (16 * 20);
    #pragma unroll
    for (int mi = 0; mi < 4; mi++)
        #pragma unroll
        for (int ni = 0; ni < 2; ni++) {
            wmma::store_matrix_sync(stg, acc[mi][ni], 20, wmma::mem_row_major);
            __syncwarp();
            int r0 = m0 + wm * 64 + mi * 16;
            int c0 = n0 + wn * 32 + ni * 16;
            if (headmajor) {
                int h = c0 >> 6, dbase = c0 & 63;
                #pragma unroll
                for (int e = lane; e < 256; e += 32) {
                    int r = e >> 4, c = e & 15;
                    int grow = r0 + r;
                    int bb_ = grow >> 9, nn_ = grow & 511;
                    C[(((size_t)bb_ * HH + h) * NSEQ + nn_) * DK + dbase + c] =
                        stg[r * 20 + c] + bias[c0 + c];
                }
            } else {
                #pragma unroll
                for (int e = lane; e < 256; e += 32) {
                    int r = e >> 4, c = e & 15;
                    C[(size_t)(r0 + r) * Nn + c0 + c] = stg[r * 20 + c] + bias[c0 + c];
                }
            }
            __syncwarp();
        }
}

// ---------------- Fused attention v3: double-buffered 64-key chunks ----------------
// 32 queries x 512 keys per CTA, one (b,h). 8 warps, 2 CTA/SM.
#define PLD 516
#define QLD 68
#define KLD 68
#define KCH 64    // keys per chunk
#define NCH 8     // chunks

__global__ __launch_bounds__(256, 2) void attn_kernel(const float* __restrict__ q,
                                                      const float* __restrict__ k,
                                                      const float* __restrict__ v,
                                                      const int* __restrict__ px,
                                                      const int* __restrict__ py,
                                                      const float* __restrict__ demb,
                                                      float* __restrict__ att,
                                                      float* __restrict__ oh) {
    extern __shared__ float sm[];
    float* Ps   = sm;                               // [32][PLD]
    float* Qs   = sm + 32 * PLD;                    // [32][QLD]  (later: output staging)
    float* KVs  = Qs + 32 * QLD;                    // [2][KCH][KLD] ping-pong
    int*   pxyk = (int*)(KVs + 2 * KCH * KLD);      // [512]
    int*   pxyq = pxyk + 512;                       // [32]
    float* db2  = (float*)(pxyq + 32);              // [441]

    int q0 = blockIdx.x * 32;
    int h  = blockIdx.y;
    int b  = blockIdx.z;
    int tid = threadIdx.x;
    int w = tid >> 5, lane = tid & 31;

    const float* qh = q + ((size_t)(b * HH + h) * NSEQ) * DK;
    const float* kh = k + ((size_t)(b * HH + h) * NSEQ) * DK;
    const float* vh = v + ((size_t)(b * HH + h) * NSEQ) * DK;

    // stage Q + K chunks 0,1 (separate commit groups: Q+K0, then K1)
    for (int i = tid; i < 32 * 16; i += 256) {
        int r = i >> 4, c4 = i & 15;
        cp_async16(Qs + r * QLD + c4 * 4, qh + (size_t)(q0 + r) * DK + c4 * 4);
    }
    for (int i = tid; i < KCH * 16; i += 256) {
        int r = i >> 4, c4 = i & 15;
        cp_async16(KVs + r * KLD + c4 * 4, kh + (size_t)r * DK + c4 * 4);
    }
    asm volatile("cp.async.commit_group;\n" ::: "memory");
    for (int i = tid; i < KCH * 16; i += 256) {
        int r = i >> 4, c4 = i & 15;
        cp_async16(KVs + KCH * KLD + r * KLD + c4 * 4, kh + (size_t)(KCH + r) * DK + c4 * 4);
    }
    asm volatile("cp.async.commit_group;\n" ::: "memory");

    for (int c = tid; c < 512; c += 256)
        pxyk[c] = px[b * NSEQ + c] | (py[b * NSEQ + c] << 16);
    if (tid < 32)
        pxyq[tid] = px[b * NSEQ + q0 + tid] | (py[b * NSEQ + q0 + tid] << 16);
    for (int i = tid; i < 441; i += 256) {
        int dx = i / 21 - 10, dy = i % 21 - 10;
        int bin = (int)(sqrtf((float)(dx * dx + dy * dy)) * 2.0f);
        db2[i] = demb[bin * HH + h];
    }

    // ---- S = Q K^T: 8 chunks of 64 keys, ping-pong ----
    int wq = w >> 2, wk = w & 3;     // 2 q-tiles x 4 key-subtiles (16 each)
    for (int ch = 0; ch < NCH; ch++) {
        asm volatile("cp.async.wait_group 1;\n" ::: "memory");
        __syncthreads();
        float* Kb = KVs + (ch & 1) * KCH * KLD;

        wmma::fragment<wmma::accumulator, 16, 16, 8, float> sa, sb;
        wmma::fill_fragment(sa, 0.0f);
        wmma::fill_fragment(sb, 0.0f);
        #pragma unroll
        for (int kk = 0; kk < DK; kk += 8) {
            wmma::fragment<wmma::matrix_a, 16, 16, 8, wmma::precision::tf32, wmma::row_major> af;
            wmma::load_matrix_sync(af, Qs + (wq * 16) * QLD + kk, QLD);
            #pragma unroll
            for (int e = 0; e < af.num_elements; e++) af.x[e] = wmma::__float_to_tf32(af.x[e]);
            wmma::fragment<wmma::matrix_b, 16, 16, 8, wmma::precision::tf32, wmma::col_major> bf;
            wmma::load_matrix_sync(bf, Kb + (wk * 16) * KLD + kk, KLD);
            #pragma unroll
            for (int e = 0; e < bf.num_elements; e++) bf.x[e] = wmma::__float_to_tf32(bf.x[e]);
            if ((kk >> 3) & 1) wmma::mma_sync(sb, af, bf, sb);
            else               wmma::mma_sync(sa, af, bf, sa);
        }
        #pragma unroll
        for (int e = 0; e < sa.num_elements; e++) sa.x[e] = (sa.x[e] + sb.x[e]) * 0.125f;
        wmma::store_matrix_sync(&Ps[(wq * 16) * PLD + ch * KCH + wk * 16], sa, PLD,
                                wmma::mem_row_major);
        __syncthreads();
        if (ch + 2 < NCH) {
            const float* src = kh + (size_t)((ch + 2) * KCH) * DK;
            float* dst = KVs + (ch & 1) * KCH * KLD;
            for (int i = tid; i < KCH * 16; i += 256) {
                int r = i >> 4, c4 = i & 15;
                cp_async16(dst + r * KLD + c4 * 4, src + (size_t)r * DK + c4 * 4);
            }
        }
        asm volatile("cp.async.commit_group;\n" ::: "memory");
    }

    // prefetch V chunks 0,1 (hidden under softmax)
    for (int pc = 0; pc < 2; pc++) {
        const float* src = vh + (size_t)(pc * KCH) * DK;
        float* dst = KVs + pc * KCH * KLD;
        for (int i = tid; i < KCH * 16; i += 256) {
            int r = i >> 4, c4 = i & 15;
            cp_async16(dst + r * KLD + c4 * 4, src + (size_t)r * DK + c4 * 4);
        }
        asm volatile("cp.async.commit_group;\n" ::: "memory");
    }

    // ---- bias + softmax (float4, __expf); att written with streaming stores ----
    float* attb = att + ((size_t)(b * HH + h) * NSEQ + q0) * NSEQ;
    for (int rr = 0; rr < 4; rr++) {
        int r = w * 4 + rr;
        int pq = pxyq[r];
        int pxr = pq & 0xffff, pyr = pq >> 16;
        float mx = -1e30f;
        #pragma unroll
        for (int i = 0; i < 4; i++) {
            int c0 = i * 128 + lane * 4;
            float4 s = *(float4*)&Ps[r * PLD + c0];
            int4 pk = *(int4*)&pxyk[c0];
            s.x += db2[((pk.x & 0xffff) - pxr + 10) * 21 + ((pk.x >> 16) - pyr + 10)];
            s.y += db2[((pk.y & 0xffff) - pxr + 10) * 21 + ((pk.y >> 16) - pyr + 10)];
            s.z += db2[((pk.z & 0xffff) - pxr + 10) * 21 + ((pk.z >> 16) - pyr + 10)];
            s.w += db2[((pk.w & 0xffff) - pxr + 10) * 21 + ((pk.w >> 16) - pyr + 10)];
            *(float4*)&Ps[r * PLD + c0] = s;
            mx = fmaxf(mx, fmaxf(fmaxf(s.x, s.y), fmaxf(s.z, s.w)));
        }
        #pragma unroll
        for (int o = 16; o; o >>= 1) mx = fmaxf(mx, __shfl_xor_sync(0xffffffffu, mx, o));
        float sum = 0.f;
        #pragma unroll
        for (int i = 0; i < 4; i++) {
            int c0 = i * 128 + lane * 4;
            float4 s = *(float4*)&Ps[r * PLD + c0];
            s.x = __expf(s.x - mx); s.y = __expf(s.y - mx);
            s.z = __expf(s.z - mx); s.w = __expf(s.w - mx);
            *(float4*)&Ps[r * PLD + c0] = s;
            sum += s.x + s.y + s.z + s.w;
        }
        #pragma unroll
        for (int o = 16; o; o >>= 1) sum += __shfl_xor_sync(0xffffffffu, sum, o);
        float inv = 1.0f / sum;
        #pragma unroll
        for (int i = 0; i < 4; i++) {
            int c0 = i * 128 + lane * 4;
            float4 s = *(float4*)&Ps[r * PLD + c0];
            s.x *= inv; s.y *= inv; s.z *= inv; s.w *= inv;
            *(float4*)&Ps[r * PLD + c0] = s;
            __stcs((float4*)&attb[(size_t)r * NSEQ + c0], s);
        }
    }
    __syncthreads();

    // ---- out = P V: 8 chunks, ping-pong, 2 acc chains per warp ----
    int q_mi = w >> 2, n_i = w & 3;
    wmma::fragment<wmma::accumulator, 16, 16, 8, float> oa, ob;
    wmma::fill_fragment(oa, 0.0f);
    wmma::fill_fragment(ob, 0.0f);
    for (int ch = 0; ch < NCH; ch++) {
        asm volatile("cp.async.wait_group 1;\n" ::: "memory");
        __syncthreads();
        float* Vb = KVs + (ch & 1) * KCH * KLD;
        #pragma unroll
        for (int kk = 0; kk < KCH; kk += 8) {
            wmma::fragment<wmma::matrix_a, 16, 16, 8, wmma::precision::tf32, wmma::row_major> a2;
            wmma::load_matrix_sync(a2, &Ps[(q_mi * 16) * PLD + ch * KCH + kk], PLD);
            #pragma unroll
            for (int e = 0; e < a2.num_elements; e++) a2.x[e] = wmma::__float_to_tf32(a2.x[e]);
            wmma::fragment<wmma::matrix_b, 16, 16, 8, wmma::precision::tf32, wmma::row_major> b2;
            wmma::load_matrix_sync(b2, Vb + kk * KLD + n_i * 16, KLD);
            #pragma unroll
            for (int e = 0; e < b2.num_elements; e++) b2.x[e] = wmma::__float_to_tf32(b2.x[e]);
            if ((kk >> 3) & 1) wmma::mma_sync(ob, a2, b2, ob);
            else               wmma::mma_sync(oa, a2, b2, oa);
        }
        __syncthreads();
        if (ch + 2 < NCH) {
            const float* src = vh + (size_t)((ch + 2) * KCH) * DK;
            float* dst = KVs + (ch & 1) * KCH * KLD;
            for (int i = tid; i < KCH * 16; i += 256) {
                int r = i >> 4, c4 = i & 15;
                cp_async16(dst + r * KLD + c4 * 4, src + (size_t)r * DK + c4 * 4);
            }
        }
        asm volatile("cp.async.commit_group;\n" ::: "memory");
    }

    // epilogue: combine chains, stage 32x64 in Qs, coalesced float4 write
    #pragma unroll
    for (int e = 0; e < oa.num_elements; e++) oa.x[e] += ob.x[e];
    wmma::store_matrix_sync(Qs + (q_mi * 16) * QLD + n_i * 16, oa, QLD, wmma::mem_row_major);
    __syncthreads();
    for (int i = tid; i < 512; i += 256) {
        int r = i >> 4, c4 = i & 15;
        float4 val = *(float4*)&Qs[r * QLD + c4 * 4];
        *(float4*)&oh[((size_t)(b * NSEQ + q0 + r)) * DM + h * DK + c4 * 4] = val;
    }
}

// ---------------- launch ----------------
extern "C" void kernel_launch(void* const* d_in, const int* in_sizes, int n_in,
                              void* d_out, int out_size) {
    const float* features = (const float*)d_in[0];
    const float* boxes    = (const float*)d_in[1];
    const int*   img      = (const int*)d_in[2];
    const float* Wq = (const float*)d_in[3];  const float* bq = (const float*)d_in[4];
    const float* Wk = (const float*)d_in[5];  const float* bk = (const float*)d_in[6];
    const float* Wv = (const float*)d_in[7];  const float* bv = (const float*)d_in[8];
    const float* Wo = (const float*)d_in[9];  const float* bo = (const float*)d_in[10];
    const float* gamma = (const float*)d_in[11];
    const float* beta  = (const float*)d_in[12];
    const float* demb  = (const float*)d_in[13];

    float* out = (float*)d_out;                       // (B, N, D)
    float* att = out + (size_t)BB * NSEQ * DM;        // (B, H, N, N)

    float *xln, *qb, *kb, *vb, *ohb;
    int *pxp, *pyp;
    cudaGetSymbolAddress((void**)&xln, g_xln);
    cudaGetSymbolAddress((void**)&qb,  g_q);
    cudaGetSymbolAddress((void**)&kb,  g_k);
    cudaGetSymbolAddress((void**)&vb,  g_v);
    cudaGetSymbolAddress((void**)&ohb, g_oh);
    cudaGetSymbolAddress((void**)&pxp, g_px);
    cudaGetSymbolAddress((void**)&pyp, g_py);

    ln_kernel<<<MTOT, 256>>>(features, gamma, beta, xln);
    bins_kernel<<<(MTOT + 255) / 256, 256>>>(boxes, img, pxp, pyp);

    int gsmem = GST * (GBM * GLD + GBN * GLD) * 4;   // 110592 B
    cudaFuncSetAttribute(gemm_tf32_pipe, cudaFuncAttributeMaxDynamicSharedMemorySize, gsmem);

    // fused QKV (head-major outputs)
    dim3 gqkv(DM / GBN, MTOT / GBM, 3);
    gemm_tf32_pipe<<<gqkv, 256, gsmem>>>(xln, Wq, Wk, Wv, bq, bk, bv, qb, kb, vb,
                                         MTOT, DM, DM, 1);

    int asmem = (32 * PLD + 32 * QLD + 2 * KCH * KLD) * 4 + 512 * 4 + 32 * 4 + 441 * 4;
    cudaFuncSetAttribute(attn_kernel, cudaFuncAttributeMaxDynamicSharedMemorySize, asmem);
    attn_kernel<<<dim3(NSEQ / 32, HH, BB), 256, asmem>>>(qb, kb, vb, pxp, pyp, demb, att, ohb);

    dim3 go(DM / GBN, MTOT / GBM, 1);
    gemm_tf32_pipe<<<go, 256, gsmem>>>(ohb, Wo, Wo, Wo, bo, bo, bo, out, out, out,
                                       MTOT, DM, DM, 0);
}

// round 16
// speedup vs baseline: 1.0401x; 1.0401x over previous
#include <cuda_runtime.h>
#include <mma.h>
#include <cstdint>
#include <cstdio>

using namespace nvcuda;

// Problem constants
#define BB   16
#define NSEQ 512
#define DM   768
#define HH   12
#define DK   64
#define NDE  32

#define MTOT (BB * NSEQ)   // 8192 rows

// ---------------- scratch (device globals; allocation-free) ----------------
__device__ float g_xln[MTOT * DM];
__device__ float g_q[MTOT * DM];     // head-major (B,H,N,DK)
__device__ float g_k[MTOT * DM];     // head-major
__device__ float g_v[MTOT * DM];     // head-major
__device__ float g_oh[MTOT * DM];    // token-major (B,N,D)
__device__ int   g_px[MTOT];
__device__ int   g_py[MTOT];

// ---------------- LayerNorm + fused patch-bin computation ----------------
__global__ __launch_bounds__(256) void ln_kernel(const float* __restrict__ x,
                                                 const float* __restrict__ gamma,
                                                 const float* __restrict__ beta,
                                                 const float* __restrict__ boxes,
                                                 const int* __restrict__ img,
                                                 float* __restrict__ y,
                                                 int* __restrict__ px,
                                                 int* __restrict__ py) {
    int row = blockIdx.x;
    int tid = threadIdx.x;

    // thread 0: patch bins for this token (overlaps with the loads below)
    if (tid == 0) {
        int b = row >> 9;
        float wf = (float)img[b * 4 + 0];
        float hf = (float)img[b * 4 + 1];
        const float* bx = boxes + (size_t)row * 4;
        float spa_w = floorf(wf / 11.0f);
        float spa_h = floorf(hf / 11.0f);
        float cx = floorf((bx[0] * wf + bx[2] * wf) * 0.5f);
        float cy = floorf((bx[1] * hf + bx[3] * hf) * 0.5f);
        int pxi = 0, pyi = 0;
        for (int i = 0; i < 11; i++) {
            float lo = (float)i * spa_w, hi = (float)(i + 1) * spa_w;
            if (lo <= cx && cx <= hi) { pxi = i; break; }
        }
        for (int i = 0; i < 11; i++) {
            float lo = (float)i * spa_h, hi = (float)(i + 1) * spa_h;
            if (lo <= cy && cy <= hi) { pyi = i; break; }
        }
        px[row] = pxi;
        py[row] = pyi;
    }

    const float* xr = x + (size_t)row * DM;
    float v0 = xr[tid], v1 = xr[tid + 256], v2 = xr[tid + 512];
    __shared__ float red[256];
    red[tid] = v0 + v1 + v2;
    __syncthreads();
    for (int o = 128; o; o >>= 1) { if (tid < o) red[tid] += red[tid + o]; __syncthreads(); }
    float mean = red[0] * (1.0f / 768.0f);
    __syncthreads();
    float d0 = v0 - mean, d1 = v1 - mean, d2 = v2 - mean;
    red[tid] = d0 * d0 + d1 * d1 + d2 * d2;
    __syncthreads();
    for (int o = 128; o; o >>= 1) { if (tid < o) red[tid] += red[tid + o]; __syncthreads(); }
    float rs = rsqrtf(red[0] * (1.0f / 768.0f) + 1e-5f);
    float* yr = y + (size_t)row * DM;
    yr[tid]       = d0 * rs * gamma[tid]       + beta[tid];
    yr[tid + 256] = d1 * rs * gamma[tid + 256] + beta[tid + 256];
    yr[tid + 512] = d2 * rs * gamma[tid + 512] + beta[tid + 512];
}

// ---------------- 3-stage pipelined TF32 GEMM: C = A @ W^T + bias ----------------
#define GBM 128
#define GBN 128
#define GBK 32
#define GLD 36
#define GST 3

__device__ __forceinline__ void cp_async16(void* smem, const void* gmem) {
    uint32_t s = (uint32_t)__cvta_generic_to_shared(smem);
    asm volatile("cp.async.cg.shared.global [%0], [%1], 16;\n" :: "r"(s), "l"(gmem));
}

__global__ __launch_bounds__(256, 2) void gemm_tf32_pipe(
    const float* __restrict__ A,
    const float* __restrict__ W0, const float* __restrict__ W1, const float* __restrict__ W2,
    const float* __restrict__ b0, const float* __restrict__ b1, const float* __restrict__ b2,
    float* __restrict__ C0, float* __restrict__ C1, float* __restrict__ C2,
    int M, int Nn, int K, int headmajor)
{
    extern __shared__ float sm[];
    float* As = sm;                        // [3][GBM][GLD]
    float* Bs = sm + GST * GBM * GLD;      // [3][GBN][GLD]

    const float* W    = blockIdx.z == 0 ? W0 : blockIdx.z == 1 ? W1 : W2;
    const float* bias = blockIdx.z == 0 ? b0 : blockIdx.z == 1 ? b1 : b2;
    float*       C    = blockIdx.z == 0 ? C0 : blockIdx.z == 1 ? C1 : C2;

    int tid = threadIdx.x;
    int w = tid >> 5, lane = tid & 31;
    int wm = w >> 2, wn = w & 3;
    int m0 = blockIdx.y * GBM;
    int n0 = blockIdx.x * GBN;

    wmma::fragment<wmma::accumulator, 16, 16, 8, float> acc[4][2];
    #pragma unroll
    for (int i = 0; i < 4; i++)
        #pragma unroll
        for (int j = 0; j < 2; j++) wmma::fill_fragment(acc[i][j], 0.0f);

    int r_ld  = tid >> 3;
    int c4_ld = (tid & 7) * 4;

    const int NIT = K / GBK;

    #pragma unroll
    for (int pc = 0; pc < 2; pc++) {
        float* Ab = As + pc * GBM * GLD;
        float* Bb = Bs + pc * GBN * GLD;
        int k0 = pc * GBK;
        #pragma unroll
        for (int j = 0; j < 4; j++) {
            int r = r_ld + j * 32;
            cp_async16(Ab + r * GLD + c4_ld, A + (size_t)(m0 + r) * K + k0 + c4_ld);
            cp_async16(Bb + r * GLD + c4_ld, W + (size_t)(n0 + r) * K + k0 + c4_ld);
        }
        asm volatile("cp.async.commit_group;\n" ::: "memory");
    }

    for (int it = 0; it < NIT; it++) {
        asm volatile("cp.async.wait_group 1;\n" ::: "memory");
        __syncthreads();
        int in = it + 2;
        if (in < NIT) {
            int k0 = in * GBK;
            float* Ab = As + (in % GST) * GBM * GLD;
            float* Bb = Bs + (in % GST) * GBN * GLD;
            #pragma unroll
            for (int j = 0; j < 4; j++) {
                int r = r_ld + j * 32;
                cp_async16(Ab + r * GLD + c4_ld, A + (size_t)(m0 + r) * K + k0 + c4_ld);
                cp_async16(Bb + r * GLD + c4_ld, W + (size_t)(n0 + r) * K + k0 + c4_ld);
            }
        }
        asm volatile("cp.async.commit_group;\n" ::: "memory");

        float* Ab = As + (it % GST) * GBM * GLD;
        float* Bb = Bs + (it % GST) * GBN * GLD;
        #pragma unroll
        for (int ks = 0; ks < 4; ks++) {
            wmma::fragment<wmma::matrix_a, 16, 16, 8, wmma::precision::tf32, wmma::row_major> af[4];
            wmma::fragment<wmma::matrix_b, 16, 16, 8, wmma::precision::tf32, wmma::col_major> bf[2];
            #pragma unroll
            for (int mi = 0; mi < 4; mi++) {
                wmma::load_matrix_sync(af[mi], Ab + (wm * 64 + mi * 16) * GLD + ks * 8, GLD);
                #pragma unroll
                for (int e = 0; e < af[mi].num_elements; e++)
                    af[mi].x[e] = wmma::__float_to_tf32(af[mi].x[e]);
            }
            #pragma unroll
            for (int ni = 0; ni < 2; ni++) {
                wmma::load_matrix_sync(bf[ni], Bb + (wn * 32 + ni * 16) * GLD + ks * 8, GLD);
                #pragma unroll
                for (int e = 0; e < bf[ni].num_elements; e++)
                    bf[ni].x[e] = wmma::__float_to_tf32(bf[ni].x[e]);
            }
            #pragma unroll
            for (int mi = 0; mi < 4; mi++)
                #pragma unroll
                for (int ni = 0; ni < 2; ni++)
                    wmma::mma_sync(acc[mi][ni], af[mi], bf[ni], acc[mi][ni]);
        }
    }
    __syncthreads();

    float* stg = sm + w * (16 * 20);
    #pragma unroll
    for (int mi = 0; mi < 4; mi++)
        #pragma unroll
        for (int ni = 0; ni < 2; ni++) {
            wmma::store_matrix_sync(stg, acc[mi][ni], 20, wmma::mem_row_major);
            __syncwarp();
            int r0 = m0 + wm * 64 + mi * 16;
            int c0 = n0 + wn * 32 + ni * 16;
            if (headmajor) {
                int h = c0 >> 6, dbase = c0 & 63;
                #pragma unroll
                for (int e = lane; e < 256; e += 32) {
                    int r = e >> 4, c = e & 15;
                    int grow = r0 + r;
                    int bb_ = grow >> 9, nn_ = grow & 511;
                    C[(((size_t)bb_ * HH + h) * NSEQ + nn_) * DK + dbase + c] =
                        stg[r * 20 + c] + bias[c0 + c];
                }
            } else {
                #pragma unroll
                for (int e = lane; e < 256; e += 32) {
                    int r = e >> 4, c = e & 15;
                    C[(size_t)(r0 + r) * Nn + c0 + c] = stg[r * 20 + c] + bias[c0 + c];
                }
            }
            __syncwarp();
        }
}

// ---------------- Fused attention v4: register-cached Q fragments ----------------
// 32 queries x 512 keys per CTA, one (b,h). 8 warps, 2 CTA/SM.
#define PLD 516
#define QLD 68
#define KLD 68
#define KCH 64    // keys per chunk
#define NCH 8     // chunks

__global__ __launch_bounds__(256, 2) void attn_kernel(const float* __restrict__ q,
                                                      const float* __restrict__ k,
                                                      const float* __restrict__ v,
                                                      const int* __restrict__ px,
                                                      const int* __restrict__ py,
                                                      const float* __restrict__ demb,
                                                      float* __restrict__ att,
                                                      float* __restrict__ oh) {
    extern __shared__ float sm[];
    float* Ps   = sm;                               // [32][PLD]
    float* Qs   = sm + 32 * PLD;                    // [32][QLD]  (later: output staging)
    float* KVs  = Qs + 32 * QLD;                    // [2][KCH][KLD] ping-pong
    int*   pxyk = (int*)(KVs + 2 * KCH * KLD);      // [512]
    int*   pxyq = pxyk + 512;                       // [32]
    float* db2  = (float*)(pxyq + 32);              // [441]

    int q0 = blockIdx.x * 32;
    int h  = blockIdx.y;
    int b  = blockIdx.z;
    int tid = threadIdx.x;
    int w = tid >> 5, lane = tid & 31;

    const float* qh = q + ((size_t)(b * HH + h) * NSEQ) * DK;
    const float* kh = k + ((size_t)(b * HH + h) * NSEQ) * DK;
    const float* vh = v + ((size_t)(b * HH + h) * NSEQ) * DK;

    // stage Q + K chunk0 (group 0), K chunk1 (group 1)
    for (int i = tid; i < 32 * 16; i += 256) {
        int r = i >> 4, c4 = i & 15;
        cp_async16(Qs + r * QLD + c4 * 4, qh + (size_t)(q0 + r) * DK + c4 * 4);
    }
    for (int i = tid; i < KCH * 16; i += 256) {
        int r = i >> 4, c4 = i & 15;
        cp_async16(KVs + r * KLD + c4 * 4, kh + (size_t)r * DK + c4 * 4);
    }
    asm volatile("cp.async.commit_group;\n" ::: "memory");
    for (int i = tid; i < KCH * 16; i += 256) {
        int r = i >> 4, c4 = i & 15;
        cp_async16(KVs + KCH * KLD + r * KLD + c4 * 4, kh + (size_t)(KCH + r) * DK + c4 * 4);
    }
    asm volatile("cp.async.commit_group;\n" ::: "memory");

    for (int c = tid; c < 512; c += 256)
        pxyk[c] = px[b * NSEQ + c] | (py[b * NSEQ + c] << 16);
    if (tid < 32)
        pxyq[tid] = px[b * NSEQ + q0 + tid] | (py[b * NSEQ + q0 + tid] << 16);
    for (int i = tid; i < 441; i += 256) {
        int dx = i / 21 - 10, dy = i % 21 - 10;
        int bin = (int)(sqrtf((float)(dx * dx + dy * dy)) * 2.0f);
        db2[i] = demb[bin * HH + h];
    }

    // wait for Q + K0, then cache this warp's 8 Q k-step fragments in registers
    asm volatile("cp.async.wait_group 1;\n" ::: "memory");
    __syncthreads();

    int wq = w >> 2, wk = w & 3;     // 2 q-tiles x 4 key-subtiles (16 each)
    wmma::fragment<wmma::matrix_a, 16, 16, 8, wmma::precision::tf32, wmma::row_major> qf[8];
    #pragma unroll
    for (int kk8 = 0; kk8 < 8; kk8++) {
        wmma::load_matrix_sync(qf[kk8], Qs + (wq * 16) * QLD + kk8 * 8, QLD);
        #pragma unroll
        for (int e = 0; e < qf[kk8].num_elements; e++)
            qf[kk8].x[e] = wmma::__float_to_tf32(qf[kk8].x[e]);
    }

    // ---- S = Q K^T: 8 chunks of 64 keys, ping-pong ----
    for (int ch = 0; ch < NCH; ch++) {
        if (ch > 0) {
            asm volatile("cp.async.wait_group 1;\n" ::: "memory");
            __syncthreads();
        }
        float* Kb = KVs + (ch & 1) * KCH * KLD;

        wmma::fragment<wmma::accumulator, 16, 16, 8, float> sa, sb;
        wmma::fill_fragment(sa, 0.0f);
        wmma::fill_fragment(sb, 0.0f);
        #pragma unroll
        for (int kk8 = 0; kk8 < 8; kk8++) {
            wmma::fragment<wmma::matrix_b, 16, 16, 8, wmma::precision::tf32, wmma::col_major> bf;
            wmma::load_matrix_sync(bf, Kb + (wk * 16) * KLD + kk8 * 8, KLD);
            #pragma unroll
            for (int e = 0; e < bf.num_elements; e++) bf.x[e] = wmma::__float_to_tf32(bf.x[e]);
            if (kk8 & 1) wmma::mma_sync(sb, qf[kk8], bf, sb);
            else         wmma::mma_sync(sa, qf[kk8], bf, sa);
        }
        #pragma unroll
        for (int e = 0; e < sa.num_elements; e++) sa.x[e] = (sa.x[e] + sb.x[e]) * 0.125f;
        wmma::store_matrix_sync(&Ps[(wq * 16) * PLD + ch * KCH + wk * 16], sa, PLD,
                                wmma::mem_row_major);
        __syncthreads();
        if (ch + 2 < NCH) {
            const float* src = kh + (size_t)((ch + 2) * KCH) * DK;
            float* dst = KVs + (ch & 1) * KCH * KLD;
            for (int i = tid; i < KCH * 16; i += 256) {
                int r = i >> 4, c4 = i & 15;
                cp_async16(dst + r * KLD + c4 * 4, src + (size_t)r * DK + c4 * 4);
            }
        }
        asm volatile("cp.async.commit_group;\n" ::: "memory");
    }

    // prefetch V chunks 0,1 (hidden under softmax)
    for (int pc = 0; pc < 2; pc++) {
        const float* src = vh + (size_t)(pc * KCH) * DK;
        float* dst = KVs + pc * KCH * KLD;
        for (int i = tid; i < KCH * 16; i += 256) {
            int r = i >> 4, c4 = i & 15;
            cp_async16(dst + r * KLD + c4 * 4, src + (size_t)r * DK + c4 * 4);
        }
        asm volatile("cp.async.commit_group;\n" ::: "memory");
    }

    // ---- bias + softmax (float4, __expf); att written with streaming stores ----
    float* attb = att + ((size_t)(b * HH + h) * NSEQ + q0) * NSEQ;
    for (int rr = 0; rr < 4; rr++) {
        int r = w * 4 + rr;
        int pq = pxyq[r];
        int pxr = pq & 0xffff, pyr = pq >> 16;
        float mx = -1e30f;
        #pragma unroll
        for (int i = 0; i < 4; i++) {
            int c0 = i * 128 + lane * 4;
            float4 s = *(float4*)&Ps[r * PLD + c0];
            int4 pk = *(int4*)&pxyk[c0];
            s.x += db2[((pk.x & 0xffff) - pxr + 10) * 21 + ((pk.x >> 16) - pyr + 10)];
            s.y += db2[((pk.y & 0xffff) - pxr + 10) * 21 + ((pk.y >> 16) - pyr + 10)];
            s.z += db2[((pk.z & 0xffff) - pxr + 10) * 21 + ((pk.z >> 16) - pyr + 10)];
            s.w += db2[((pk.w & 0xffff) - pxr + 10) * 21 + ((pk.w >> 16) - pyr + 10)];
            *(float4*)&Ps[r * PLD + c0] = s;
            mx = fmaxf(mx, fmaxf(fmaxf(s.x, s.y), fmaxf(s.z, s.w)));
        }
        #pragma unroll
        for (int o = 16; o; o >>= 1) mx = fmaxf(mx, __shfl_xor_sync(0xffffffffu, mx, o));
        float sum = 0.f;
        #pragma unroll
        for (int i = 0; i < 4; i++) {
            int c0 = i * 128 + lane * 4;
            float4 s = *(float4*)&Ps[r * PLD + c0];
            s.x = __expf(s.x - mx); s.y = __expf(s.y - mx);
            s.z = __expf(s.z - mx); s.w = __expf(s.w - mx);
            *(float4*)&Ps[r * PLD + c0] = s;
            sum += s.x + s.y + s.z + s.w;
        }
        #pragma unroll
        for (int o = 16; o; o >>= 1) sum += __shfl_xor_sync(0xffffffffu, sum, o);
        float inv = 1.0f / sum;
        #pragma unroll
        for (int i = 0; i < 4; i++) {
            int c0 = i * 128 + lane * 4;
            float4 s = *(float4*)&Ps[r * PLD + c0];
            s.x *= inv; s.y *= inv; s.z *= inv; s.w *= inv;
            *(float4*)&Ps[r * PLD + c0] = s;
            __stcs((float4*)&attb[(size_t)r * NSEQ + c0], s);
        }
    }
    __syncthreads();

    // ---- out = P V: 8 chunks, ping-pong, 2 acc chains per warp ----
    int q_mi = w >> 2, n_i = w & 3;
    wmma::fragment<wmma::accumulator, 16, 16, 8, float> oa, ob;
    wmma::fill_fragment(oa, 0.0f);
    wmma::fill_fragment(ob, 0.0f);
    for (int ch = 0; ch < NCH; ch++) {
        asm volatile("cp.async.wait_group 1;\n" ::: "memory");
        __syncthreads();
        float* Vb = KVs + (ch & 1) * KCH * KLD;
        #pragma unroll
        for (int kk = 0; kk < KCH; kk += 8) {
            wmma::fragment<wmma::matrix_a, 16, 16, 8, wmma::precision::tf32, wmma::row_major> a2;
            wmma::load_matrix_sync(a2, &Ps[(q_mi * 16) * PLD + ch * KCH + kk], PLD);
            #pragma unroll
            for (int e = 0; e < a2.num_elements; e++) a2.x[e] = wmma::__float_to_tf32(a2.x[e]);
            wmma::fragment<wmma::matrix_b, 16, 16, 8, wmma::precision::tf32, wmma::row_major> b2;
            wmma::load_matrix_sync(b2, Vb + kk * KLD + n_i * 16, KLD);
            #pragma unroll
            for (int e = 0; e < b2.num_elements; e++) b2.x[e] = wmma::__float_to_tf32(b2.x[e]);
            if ((kk >> 3) & 1) wmma::mma_sync(ob, a2, b2, ob);
            else               wmma::mma_sync(oa, a2, b2, oa);
        }
        __syncthreads();
        if (ch + 2 < NCH) {
            const float* src = vh + (size_t)((ch + 2) * KCH) * DK;
            float* dst = KVs + (ch & 1) * KCH * KLD;
            for (int i = tid; i < KCH * 16; i += 256) {
                int r = i >> 4, c4 = i & 15;
                cp_async16(dst + r * KLD + c4 * 4, src + (size_t)r * DK + c4 * 4);
            }
        }
        asm volatile("cp.async.commit_group;\n" ::: "memory");
    }

    // epilogue: combine chains, stage 32x64 in Qs, coalesced float4 write
    #pragma unroll
    for (int e = 0; e < oa.num_elements; e++) oa.x[e] += ob.x[e];
    wmma::store_matrix_sync(Qs + (q_mi * 16) * QLD + n_i * 16, oa, QLD, wmma::mem_row_major);
    __syncthreads();
    for (int i = tid; i < 512; i += 256) {
        int r = i >> 4, c4 = i & 15;
        float4 val = *(float4*)&Qs[r * QLD + c4 * 4];
        *(float4*)&oh[((size_t)(b * NSEQ + q0 + r)) * DM + h * DK + c4 * 4] = val;
    }
}

// ---------------- launch ----------------
extern "C" void kernel_launch(void* const* d_in, const int* in_sizes, int n_in,
                              void* d_out, int out_size) {
    const float* features = (const float*)d_in[0];
    const float* boxes    = (const float*)d_in[1];
    const int*   img      = (const int*)d_in[2];
    const float* Wq = (const float*)d_in[3];  const float* bq = (const float*)d_in[4];
    const float* Wk = (const float*)d_in[5];  const float* bk = (const float*)d_in[6];
    const float* Wv = (const float*)d_in[7];  const float* bv = (const float*)d_in[8];
    const float* Wo = (const float*)d_in[9];  const float* bo = (const float*)d_in[10];
    const float* gamma = (const float*)d_in[11];
    const float* beta  = (const float*)d_in[12];
    const float* demb  = (const float*)d_in[13];

    float* out = (float*)d_out;                       // (B, N, D)
    float* att = out + (size_t)BB * NSEQ * DM;        // (B, H, N, N)

    float *xln, *qb, *kb, *vb, *ohb;
    int *pxp, *pyp;
    cudaGetSymbolAddress((void**)&xln, g_xln);
    cudaGetSymbolAddress((void**)&qb,  g_q);
    cudaGetSymbolAddress((void**)&kb,  g_k);
    cudaGetSymbolAddress((void**)&vb,  g_v);
    cudaGetSymbolAddress((void**)&ohb, g_oh);
    cudaGetSymbolAddress((void**)&pxp, g_px);
    cudaGetSymbolAddress((void**)&pyp, g_py);

    ln_kernel<<<MTOT, 256>>>(features, gamma, beta, boxes, img, xln, pxp, pyp);

    int gsmem = GST * (GBM * GLD + GBN * GLD) * 4;   // 110592 B
    cudaFuncSetAttribute(gemm_tf32_pipe, cudaFuncAttributeMaxDynamicSharedMemorySize, gsmem);

    // fused QKV (head-major outputs)
    dim3 gqkv(DM / GBN, MTOT / GBM, 3);
    gemm_tf32_pipe<<<gqkv, 256, gsmem>>>(xln, Wq, Wk, Wv, bq, bk, bv, qb, kb, vb,
                                         MTOT, DM, DM, 1);

    int asmem = (32 * PLD + 32 * QLD + 2 * KCH * KLD) * 4 + 512 * 4 + 32 * 4 + 441 * 4;
    cudaFuncSetAttribute(attn_kernel, cudaFuncAttributeMaxDynamicSharedMemorySize, asmem);
    attn_kernel<<<dim3(NSEQ / 32, HH, BB), 256, asmem>>>(qb, kb, vb, pxp, pyp, demb, att, ohb);

    dim3 go(DM / GBN, MTOT / GBM, 1);
    gemm_tf32_pipe<<<go, 256, gsmem>>>(ohb, Wo, Wo, Wo, bo, bo, bo, out, out, out,
                                       MTOT, DM, DM, 0);
}